// round 3
// baseline (speedup 1.0000x reference)
#include <cuda_runtime.h>
#include <cuda_bf16.h>

// Problem constants
#define B   2
#define NTOK 4100
#define C   768
#define T   4
#define H   12
#define D   64
#define K   2
#define M   4096          // NTOK - T
#define J   48            // H*T query rows per batch
#define SCALE 0.125f      // d^-0.5

// ---------------- scratch (device globals; no allocations allowed) ----------
__device__ float g_q[B * T * C];                 // q[b,t,o]
__device__ float g_qk[B * J * C];                // qk[b, h*4+t, c]
__device__ float g_attn[B * J * M];              // attn[b, j, m]
__device__ int   g_topi[B * J * K];
__device__ float g_topw[B * J * K];
__device__ float g_attn_token[B * T * C];        // attn_token[b,t,c]

// ---------------- helpers ---------------------------------------------------
__device__ __forceinline__ void ffma2(unsigned long long &d,
                                      unsigned long long a,
                                      unsigned long long b) {
    asm("fma.rn.f32x2 %0, %1, %2, %0;" : "+l"(d) : "l"(a), "l"(b));
}

union U64F2 { unsigned long long u; float2 f; };

__device__ __forceinline__ float warp_sum(float s) {
    #pragma unroll
    for (int off = 16; off; off >>= 1) s += __shfl_xor_sync(0xffffffffu, s, off);
    return s;
}

// ---------------- K0: zero output -------------------------------------------
__global__ void k_zero(float4* __restrict__ out, int n4) {
    int stride = gridDim.x * blockDim.x;
    for (int i = blockIdx.x * blockDim.x + threadIdx.x; i < n4; i += stride)
        out[i] = make_float4(0.f, 0.f, 0.f, 0.f);
}

// ---------------- K1: q[b,t,o] = <x[b,t,:], qs_w[t,o,:]> --------------------
// grid 64: blk -> (b,t, o-chunk of 96). 256 threads = 8 warps, 12 outputs/warp.
__global__ __launch_bounds__(256) void k_q(const float* __restrict__ x,
                                           const float* __restrict__ qs_w) {
    int og = blockIdx.x & 7;
    int bt = blockIdx.x >> 3;
    int b = bt >> 2, t = bt & 3;
    __shared__ float xs[C];
    for (int i = threadIdx.x; i < C; i += 256)
        xs[i] = x[((long)b * NTOK + t) * C + i];
    __syncthreads();
    int warp = threadIdx.x >> 5, lane = threadIdx.x & 31;
    #pragma unroll
    for (int oo = 0; oo < 12; oo++) {
        int o = og * 96 + warp * 12 + oo;
        const float* wrow = qs_w + ((long)t * C + o) * C;
        float s = 0.f;
        for (int c = lane; c < C; c += 32) s += xs[c] * wrow[c];
        s = warp_sum(s);
        if (lane == 0) g_q[(b * T + t) * C + o] = s;
    }
}

// ---------------- K2: qk[b,j,c] = sum_dd q[b,t,h*64+dd] * kv_w[h*64+dd, c] --
// grid 288: blk -> (b, j, c-chunk of 256)
__global__ __launch_bounds__(256) void k_qk(const float* __restrict__ kv_w) {
    int ch = blockIdx.x % 3;
    int j  = (blockIdx.x / 3) % J;
    int b  = blockIdx.x / (3 * J);
    int t = j & 3, h = j >> 2;
    __shared__ float qs[D];
    if (threadIdx.x < D)
        qs[threadIdx.x] = g_q[(b * T + t) * C + h * D + threadIdx.x];
    __syncthreads();
    int c = ch * 256 + threadIdx.x;
    float acc = 0.f;
    #pragma unroll 8
    for (int dd = 0; dd < D; dd++)
        acc += qs[dd] * kv_w[(long)(h * D + dd) * C + c];
    g_qk[((long)b * J + j) * C + c] = acc;
}

// ---------------- K3: attn[b,j,m] = SCALE * <qk[b,j,:], feature[b,m,:]> -----
// grid (64 m-tiles, B). 256 threads = 8 warps.
// Warp w owns q-rows [w*6, w*6+6); lane l owns m-rows {l, l+32} of the 64-tile.
// q reads are warp-broadcast LDS (N=1) -> smem crossbar drops from 112 to
// 35 cyc/SM per cp-iter; FFMA2 issue (48 cyc) becomes the binding pipe.
#define SMS 66   // smem row stride (floats): 8B words -> bank (r*33+cp)%32, conflict-free
__global__ __launch_bounds__(256) void k_attn(const float* __restrict__ x) {
    const int b  = blockIdx.y;
    const int m0 = blockIdx.x * 64;
    __shared__ __align__(16) float qk_sm[J * SMS];
    __shared__ __align__(16) float feat_sm[64 * SMS];
    const int tid  = threadIdx.x;
    const int warp = tid >> 5;
    const int lane = tid & 31;

    unsigned long long acc[6][2];
    #pragma unroll
    for (int i = 0; i < 6; i++) { acc[i][0] = 0ull; acc[i][1] = 0ull; }

    const float* xb  = x + ((long)b * NTOK + T + m0) * C;
    const float* qkb = g_qk + (long)b * J * C;

    for (int cc = 0; cc < C; cc += 64) {
        __syncthreads();
        // qk chunk: 48 rows x 32 float2
        for (int i = tid; i < J * 32; i += 256) {
            int r = i >> 5, cp = i & 31;
            float2 v = *(const float2*)(qkb + (long)r * C + cc + cp * 2);
            *(float2*)&qk_sm[r * SMS + cp * 2] = v;
        }
        // feature chunk: 64 rows x 32 float2
        for (int i = tid; i < 64 * 32; i += 256) {
            int r = i >> 5, cp = i & 31;
            float2 v = *(const float2*)(xb + (long)r * C + cc + cp * 2);
            *(float2*)&feat_sm[r * SMS + cp * 2] = v;
        }
        __syncthreads();
        #pragma unroll 4
        for (int cp = 0; cp < 32; cp++) {
            unsigned long long f0 =
                *(const unsigned long long*)&feat_sm[lane * SMS + cp * 2];
            unsigned long long f1 =
                *(const unsigned long long*)&feat_sm[(lane + 32) * SMS + cp * 2];
            #pragma unroll
            for (int i = 0; i < 6; i++) {
                unsigned long long qv =
                    *(const unsigned long long*)&qk_sm[(warp * 6 + i) * SMS + cp * 2];
                ffma2(acc[i][0], qv, f0);
                ffma2(acc[i][1], qv, f1);
            }
        }
    }
    #pragma unroll
    for (int i = 0; i < 6; i++) {
        int j = warp * 6 + i;
        float* row = g_attn + ((long)(b * J + j)) * M + m0;
        U64F2 u0; u0.u = acc[i][0];
        U64F2 u1; u1.u = acc[i][1];
        row[lane]      = (u0.f.x + u0.f.y) * SCALE;
        row[lane + 32] = (u1.f.x + u1.f.y) * SCALE;
    }
}

// ---------------- K4: top-2 + softmax per (b,j) row -------------------------
__device__ __forceinline__ bool better(float v, int i, float bv, int bi) {
    return (v > bv) || (v == bv && (unsigned)i < (unsigned)bi);
}
__global__ __launch_bounds__(256) void k_top2() {
    const float* row = g_attn + (long)blockIdx.x * M;
    float v0 = -__int_as_float(0x7f800000), v1 = v0;  // -inf
    int i0 = -1, i1 = -1;
    for (int m = threadIdx.x; m < M; m += 256) {
        float v = row[m];
        if (better(v, m, v0, i0)) { v1 = v0; i1 = i0; v0 = v; i0 = m; }
        else if (better(v, m, v1, i1)) { v1 = v; i1 = m; }
    }
    __shared__ float sv[512];
    __shared__ int   si[512];
    sv[threadIdx.x] = v0; si[threadIdx.x] = i0;
    sv[256 + threadIdx.x] = v1; si[256 + threadIdx.x] = i1;
    __syncthreads();
    if (threadIdx.x == 0) {
        float b0 = -__int_as_float(0x7f800000), b1 = b0;
        int j0 = -1, j1 = -1;
        for (int e = 0; e < 512; e++) {
            float v = sv[e]; int i = si[e];
            if (i < 0) continue;
            if (better(v, i, b0, j0)) { b1 = b0; j1 = j0; b0 = v; j0 = i; }
            else if (better(v, i, b1, j1)) { b1 = v; j1 = i; }
        }
        // softmax over [b0, b1]  (b0 >= b1)
        float e1 = __expf(b1 - b0);
        float inv = 1.f / (1.f + e1);
        g_topi[blockIdx.x * K + 0] = j0;
        g_topi[blockIdx.x * K + 1] = j1;
        g_topw[blockIdx.x * K + 0] = inv;
        g_topw[blockIdx.x * K + 1] = e1 * inv;
    }
}

// ---------------- K5: per-selection v projection + expert scatter -----------
// grid 96 = (b,j). For each k: m = topi. Computes
//   attn_token[b,t,h*64+dd] = sum_k w_k * <feature[b,m_k,:], kv_w[768+h*64+dd,:]>
//   out[b, 4+m_k, o]       += w_k * <feature[b,m_k,h*64:+64], experts_w[t,o,h*64:+64]>
__global__ __launch_bounds__(256) void k_select(const float* __restrict__ x,
                                                const float* __restrict__ kv_w,
                                                const float* __restrict__ experts_w,
                                                float* __restrict__ out) {
    int b = blockIdx.x / J;
    int j = blockIdx.x % J;
    int t = j & 3, h = j >> 2;
    int warp = threadIdx.x >> 5, lane = threadIdx.x & 31;
    __shared__ __align__(16) float feat_sm[C];
    float accv[8];
    #pragma unroll
    for (int i = 0; i < 8; i++) accv[i] = 0.f;

    for (int k = 0; k < K; k++) {
        int   m = g_topi[blockIdx.x * K + k];
        float w = g_topw[blockIdx.x * K + k];
        __syncthreads();
        for (int i = threadIdx.x; i < C; i += 256)
            feat_sm[i] = x[((long)b * NTOK + T + m) * C + i];
        __syncthreads();

        // (a) v rows: warp handles dd = warp*8 + i
        #pragma unroll
        for (int i = 0; i < 8; i++) {
            int dd = warp * 8 + i;
            const float* kw = kv_w + (long)(C + h * D + dd) * C;
            float s = 0.f;
            for (int c = lane; c < C; c += 32) s += feat_sm[c] * kw[c];
            s = warp_sum(s);
            if (lane == 0) accv[i] += w * s;
        }

        // (b) expert projection of the selected feature head-slice
        const float4* fh4 = (const float4*)(feat_sm + h * D);
        for (int o = threadIdx.x; o < C; o += 256) {
            const float4* ew4 =
                (const float4*)(experts_w + ((long)t * C + o) * C + h * D);
            float s = 0.f;
            #pragma unroll
            for (int q = 0; q < 16; q++) {
                float4 a = fh4[q], e = ew4[q];
                s += a.x * e.x + a.y * e.y + a.z * e.z + a.w * e.w;
            }
            atomicAdd(&out[((long)b * NTOK + T + m) * C + o], w * s);
        }
    }
    if (lane == 0) {
        #pragma unroll
        for (int i = 0; i < 8; i++)
            g_attn_token[(b * T + t) * C + h * D + warp * 8 + i] = accv[i];
    }
}

// ---------------- K6: token_output[b,t,o] = <attn_token[b,t,:], experts_w[t,o,:]>
__global__ __launch_bounds__(256) void k_token(const float* __restrict__ experts_w,
                                               float* __restrict__ out) {
    int og = blockIdx.x & 7;
    int bt = blockIdx.x >> 3;
    int b = bt >> 2, t = bt & 3;
    __shared__ float as[C];
    for (int i = threadIdx.x; i < C; i += 256)
        as[i] = g_attn_token[(b * T + t) * C + i];
    __syncthreads();
    int warp = threadIdx.x >> 5, lane = threadIdx.x & 31;
    #pragma unroll
    for (int oo = 0; oo < 12; oo++) {
        int o = og * 96 + warp * 12 + oo;
        const float* wrow = experts_w + ((long)t * C + o) * C;
        float s = 0.f;
        for (int c = lane; c < C; c += 32) s += as[c] * wrow[c];
        s = warp_sum(s);
        if (lane == 0) out[((long)b * NTOK + t) * C + o] = s;
    }
}

// ---------------- launch ----------------------------------------------------
extern "C" void kernel_launch(void* const* d_in, const int* in_sizes, int n_in,
                              void* d_out, int out_size) {
    const float* x         = (const float*)d_in[0];
    const float* qs_w      = (const float*)d_in[1];
    const float* kv_w      = (const float*)d_in[2];
    const float* experts_w = (const float*)d_in[3];
    float* out = (float*)d_out;

    k_zero<<<1536, 256>>>((float4*)out, out_size / 4);
    k_q<<<64, 256>>>(x, qs_w);
    k_qk<<<288, 256>>>(kv_w);
    k_attn<<<dim3(64, B), 256>>>(x);
    k_top2<<<B * J, 256>>>();
    k_select<<<B * J, 256>>>(x, kv_w, experts_w, out);
    k_token<<<64, 256>>>(experts_w, out);
}

// round 4
// speedup vs baseline: 1.2322x; 1.2322x over previous
#include <cuda_runtime.h>
#include <cuda_bf16.h>

// Problem constants
#define B   2
#define NTOK 4100
#define C   768
#define T   4
#define H   12
#define D   64
#define K   2
#define M   4096          // NTOK - T
#define J   48            // H*T query rows per batch
#define SCALE 0.125f      // d^-0.5

// ---------------- scratch (device globals; no allocations allowed) ----------
__device__ float g_q[B * T * C];                 // q[b,t,o]
__device__ float g_qk[B * J * C];                // qk[b, h*4+t, c]
__device__ float g_attn[B * J * M];              // attn[b, j, m]
__device__ int   g_topi[B * J * K];
__device__ float g_topw[B * J * K];
__device__ float g_attn_token[B * T * C];        // attn_token[b,t,c]

// ---------------- helpers ---------------------------------------------------
__device__ __forceinline__ void ffma2(unsigned long long &d,
                                      unsigned long long a,
                                      unsigned long long b) {
    asm("fma.rn.f32x2 %0, %1, %2, %0;" : "+l"(d) : "l"(a), "l"(b));
}

union U64F2 { unsigned long long u; float2 f; };

__device__ __forceinline__ float warp_sum(float s) {
    #pragma unroll
    for (int off = 16; off; off >>= 1) s += __shfl_xor_sync(0xffffffffu, s, off);
    return s;
}

__device__ __forceinline__ void cp8(unsigned dst, const float* src) {
    asm volatile("cp.async.ca.shared.global [%0], [%1], 8;\n"
                 :: "r"(dst), "l"(__cvta_generic_to_global(src)) : "memory");
}

// ---------------- K0: zero output + g_attn_token ----------------------------
__global__ void k_zero(float4* __restrict__ out, int n4) {
    int stride = gridDim.x * blockDim.x;
    for (int i = blockIdx.x * blockDim.x + threadIdx.x; i < n4; i += stride)
        out[i] = make_float4(0.f, 0.f, 0.f, 0.f);
    if (blockIdx.x == 0) {
        for (int i = threadIdx.x; i < B * T * C; i += blockDim.x)
            g_attn_token[i] = 0.f;
    }
}

// ---------------- K1: q[b,t,o] = <x[b,t,:], qs_w[t,o,:]> --------------------
__global__ __launch_bounds__(256) void k_q(const float* __restrict__ x,
                                           const float* __restrict__ qs_w) {
    int og = blockIdx.x & 7;
    int bt = blockIdx.x >> 3;
    int b = bt >> 2, t = bt & 3;
    __shared__ float xs[C];
    for (int i = threadIdx.x; i < C; i += 256)
        xs[i] = x[((long)b * NTOK + t) * C + i];
    __syncthreads();
    int warp = threadIdx.x >> 5, lane = threadIdx.x & 31;
    #pragma unroll
    for (int oo = 0; oo < 12; oo++) {
        int o = og * 96 + warp * 12 + oo;
        const float* wrow = qs_w + ((long)t * C + o) * C;
        float s = 0.f;
        for (int c = lane; c < C; c += 32) s += xs[c] * wrow[c];
        s = warp_sum(s);
        if (lane == 0) g_q[(b * T + t) * C + o] = s;
    }
}

// ---------------- K2: qk[b,j,c] = sum_dd q[b,t,h*64+dd] * kv_w[h*64+dd, c] --
__global__ __launch_bounds__(256) void k_qk(const float* __restrict__ kv_w) {
    int ch = blockIdx.x % 3;
    int j  = (blockIdx.x / 3) % J;
    int b  = blockIdx.x / (3 * J);
    int t = j & 3, h = j >> 2;
    __shared__ float qs[D];
    if (threadIdx.x < D)
        qs[threadIdx.x] = g_q[(b * T + t) * C + h * D + threadIdx.x];
    __syncthreads();
    int c = ch * 256 + threadIdx.x;
    float acc = 0.f;
    #pragma unroll 8
    for (int dd = 0; dd < D; dd++)
        acc += qs[dd] * kv_w[(long)(h * D + dd) * C + c];
    g_qk[((long)b * J + j) * C + c] = acc;
}

// ---------------- K3: attn[b,j,m] = SCALE * <qk[b,j,:], feature[b,m,:]> -----
// grid (64 m-tiles, B). 256 threads = 8 warps.
// Double-buffered cp.async pipeline over 12 c-chunks of 64.
// smem stage layout (floats): [qk: 48 rows x 64][feat: 64 rows x 66 (pad 2)]
// qk reads are warp-broadcast (banks irrelevant); feat stride-66 gives
// pair-bank (lane + cp) mod 32 -> conflict-free.
#define QK_FL   (48 * 64)          // 3072
#define FSTR    66
#define STAGE_FL (QK_FL + 64 * FSTR)   // 7296 floats = 29184 B per stage
__global__ __launch_bounds__(256) void k_attn(const float* __restrict__ x) {
    extern __shared__ __align__(16) float sm[];   // 2 * STAGE_FL floats
    const int b  = blockIdx.y;
    const int m0 = blockIdx.x * 64;
    const int tid  = threadIdx.x;
    const int warp = tid >> 5;
    const int lane = tid & 31;

    const float* qkb = g_qk + (long)b * J * C;
    const float* xb  = x + ((long)b * NTOK + T + m0) * C;

    // per-thread copy slots: 6 qk float2 + 8 feat float2
    const float* qsrc[6]; unsigned qdst[6];
    #pragma unroll
    for (int u = 0; u < 6; u++) {
        int i = u * 256 + tid;
        int r = i >> 5, cp = i & 31;
        qsrc[u] = qkb + (long)r * C + cp * 2;
        qdst[u] = (unsigned)__cvta_generic_to_shared(&sm[r * 64 + cp * 2]);
    }
    const float* fsrc[8]; unsigned fdst[8];
    #pragma unroll
    for (int u = 0; u < 8; u++) {
        int i = u * 256 + tid;
        int r = i >> 5, cp = i & 31;
        fsrc[u] = xb + (long)r * C + cp * 2;
        fdst[u] = (unsigned)__cvta_generic_to_shared(&sm[QK_FL + r * FSTR + cp * 2]);
    }

    unsigned long long acc[6][2];
    #pragma unroll
    for (int i = 0; i < 6; i++) { acc[i][0] = 0ull; acc[i][1] = 0ull; }

    // prefetch chunk 0 into stage 0
    #pragma unroll
    for (int u = 0; u < 6; u++) cp8(qdst[u], qsrc[u]);
    #pragma unroll
    for (int u = 0; u < 8; u++) cp8(fdst[u], fsrc[u]);
    asm volatile("cp.async.commit_group;\n" ::: "memory");

    for (int ic = 0; ic < 12; ic++) {
        if (ic < 11) {
            unsigned so = ((ic + 1) & 1) * (unsigned)(STAGE_FL * 4);
            int cc = (ic + 1) * 64;
            #pragma unroll
            for (int u = 0; u < 6; u++) cp8(qdst[u] + so, qsrc[u] + cc);
            #pragma unroll
            for (int u = 0; u < 8; u++) cp8(fdst[u] + so, fsrc[u] + cc);
            asm volatile("cp.async.commit_group;\n" ::: "memory");
            asm volatile("cp.async.wait_group 1;\n" ::: "memory");
        } else {
            asm volatile("cp.async.wait_group 0;\n" ::: "memory");
        }
        __syncthreads();
        const float* s_qk = sm + (ic & 1) * STAGE_FL;
        const float* s_ft = s_qk + QK_FL;
        #pragma unroll 4
        for (int cp = 0; cp < 32; cp++) {
            unsigned long long f0 =
                *(const unsigned long long*)&s_ft[lane * FSTR + cp * 2];
            unsigned long long f1 =
                *(const unsigned long long*)&s_ft[(lane + 32) * FSTR + cp * 2];
            #pragma unroll
            for (int i = 0; i < 6; i++) {
                unsigned long long qv =
                    *(const unsigned long long*)&s_qk[(warp * 6 + i) * 64 + cp * 2];
                ffma2(acc[i][0], qv, f0);
                ffma2(acc[i][1], qv, f1);
            }
        }
        __syncthreads();
    }
    #pragma unroll
    for (int i = 0; i < 6; i++) {
        int j = warp * 6 + i;
        float* row = g_attn + ((long)(b * J + j)) * M + m0;
        U64F2 u0; u0.u = acc[i][0];
        U64F2 u1; u1.u = acc[i][1];
        row[lane]      = (u0.f.x + u0.f.y) * SCALE;
        row[lane + 32] = (u1.f.x + u1.f.y) * SCALE;
    }
}

// ---------------- K4: top-2 + softmax per (b,j) row -------------------------
__device__ __forceinline__ bool better(float v, int i, float bv, int bi) {
    return (v > bv) || (v == bv && (unsigned)i < (unsigned)bi);
}
__global__ __launch_bounds__(256) void k_top2() {
    const float* row = g_attn + (long)blockIdx.x * M;
    float v0 = -__int_as_float(0x7f800000), v1 = v0;  // -inf
    int i0 = -1, i1 = -1;
    for (int m = threadIdx.x; m < M; m += 256) {
        float v = row[m];
        if (better(v, m, v0, i0)) { v1 = v0; i1 = i0; v0 = v; i0 = m; }
        else if (better(v, m, v1, i1)) { v1 = v; i1 = m; }
    }
    __shared__ float sv[512];
    __shared__ int   si[512];
    sv[threadIdx.x] = v0; si[threadIdx.x] = i0;
    sv[256 + threadIdx.x] = v1; si[256 + threadIdx.x] = i1;
    __syncthreads();
    if (threadIdx.x == 0) {
        float b0 = -__int_as_float(0x7f800000), b1 = b0;
        int j0 = -1, j1 = -1;
        for (int e = 0; e < 512; e++) {
            float v = sv[e]; int i = si[e];
            if (i < 0) continue;
            if (better(v, i, b0, j0)) { b1 = b0; j1 = j0; b0 = v; j0 = i; }
            else if (better(v, i, b1, j1)) { b1 = v; j1 = i; }
        }
        float e1 = __expf(b1 - b0);
        float inv = 1.f / (1.f + e1);
        g_topi[blockIdx.x * K + 0] = j0;
        g_topi[blockIdx.x * K + 1] = j1;
        g_topw[blockIdx.x * K + 0] = inv;
        g_topw[blockIdx.x * K + 1] = e1 * inv;
    }
}

// ---------------- K5: per-selection v projection + expert scatter -----------
// grid 192 = (b, j, k). One selection per block.
//   attn_token[b,t,h*64+dd] += w * <feature[b,m,:], kv_w[768+h*64+dd,:]>   (atomic)
//   out[b, 4+m, o]          += w * <feature[b,m,h*64:+64], experts_w[t,o,h*64:+64]>
__global__ __launch_bounds__(256) void k_select(const float* __restrict__ x,
                                                const float* __restrict__ kv_w,
                                                const float* __restrict__ experts_w,
                                                float* __restrict__ out) {
    int sel = blockIdx.x;
    int k = sel & 1;
    int j = (sel >> 1) % J;
    int b = sel / (2 * J);
    int t = j & 3, h = j >> 2;
    int   m = g_topi[(b * J + j) * K + k];
    float w = g_topw[(b * J + j) * K + k];
    int warp = threadIdx.x >> 5, lane = threadIdx.x & 31;
    __shared__ __align__(16) float feat_sm[C];
    for (int i = threadIdx.x; i < C; i += 256)
        feat_sm[i] = x[((long)b * NTOK + T + m) * C + i];
    __syncthreads();

    // (a) v rows: warp handles dd = warp*8 + i
    #pragma unroll
    for (int i = 0; i < 8; i++) {
        int dd = warp * 8 + i;
        const float* kw = kv_w + (long)(C + h * D + dd) * C;
        float s = 0.f;
        for (int c = lane; c < C; c += 32) s += feat_sm[c] * kw[c];
        s = warp_sum(s);
        if (lane == 0)
            atomicAdd(&g_attn_token[(b * T + t) * C + h * D + dd], w * s);
    }

    // (b) expert projection of the selected feature head-slice
    float4 fa[16];
    const float4* fh4 = (const float4*)(feat_sm + h * D);
    #pragma unroll
    for (int q = 0; q < 16; q++) fa[q] = fh4[q];
    for (int o = threadIdx.x; o < C; o += 256) {
        const float4* ew4 =
            (const float4*)(experts_w + ((long)t * C + o) * C + h * D);
        float s = 0.f;
        #pragma unroll
        for (int q = 0; q < 16; q++) {
            float4 e = ew4[q];
            s += fa[q].x * e.x + fa[q].y * e.y + fa[q].z * e.z + fa[q].w * e.w;
        }
        atomicAdd(&out[((long)b * NTOK + T + m) * C + o], w * s);
    }
}

// ---------------- K6: token_output[b,t,o] = <attn_token[b,t,:], experts_w[t,o,:]>
__global__ __launch_bounds__(256) void k_token(const float* __restrict__ experts_w,
                                               float* __restrict__ out) {
    int og = blockIdx.x & 7;
    int bt = blockIdx.x >> 3;
    int b = bt >> 2, t = bt & 3;
    __shared__ float as[C];
    for (int i = threadIdx.x; i < C; i += 256)
        as[i] = g_attn_token[(b * T + t) * C + i];
    __syncthreads();
    int warp = threadIdx.x >> 5, lane = threadIdx.x & 31;
    #pragma unroll
    for (int oo = 0; oo < 12; oo++) {
        int o = og * 96 + warp * 12 + oo;
        const float* wrow = experts_w + ((long)t * C + o) * C;
        float s = 0.f;
        for (int c = lane; c < C; c += 32) s += as[c] * wrow[c];
        s = warp_sum(s);
        if (lane == 0) out[((long)b * NTOK + t) * C + o] = s;
    }
}

// ---------------- launch ----------------------------------------------------
extern "C" void kernel_launch(void* const* d_in, const int* in_sizes, int n_in,
                              void* d_out, int out_size) {
    const float* x         = (const float*)d_in[0];
    const float* qs_w      = (const float*)d_in[1];
    const float* kv_w      = (const float*)d_in[2];
    const float* experts_w = (const float*)d_in[3];
    float* out = (float*)d_out;

    cudaFuncSetAttribute(k_attn, cudaFuncAttributeMaxDynamicSharedMemorySize,
                         2 * STAGE_FL * 4);

    k_zero<<<1536, 256>>>((float4*)out, out_size / 4);
    k_q<<<64, 256>>>(x, qs_w);
    k_qk<<<288, 256>>>(kv_w);
    k_attn<<<dim3(64, B), 256, 2 * STAGE_FL * 4>>>(x);
    k_top2<<<B * J, 256>>>();
    k_select<<<192, 256>>>(x, kv_w, experts_w, out);
    k_token<<<64, 256>>>(experts_w, out);
}

// round 5
// speedup vs baseline: 1.5823x; 1.2841x over previous
#include <cuda_runtime.h>
#include <cuda_bf16.h>

// Problem constants
#define B   2
#define NTOK 4100
#define C   768
#define T   4
#define H   12
#define D   64
#define K   2
#define M   4096          // NTOK - T
#define J   48            // H*T query rows per batch
#define SCALE 0.125f      // d^-0.5

// ---------------- scratch (device globals; no allocations allowed) ----------
__device__ float g_q[B * T * C];                 // q[b,t,o]
__device__ float g_qk[B * J * C];                // qk[b, h*4+t, c]
__device__ float g_attn[B * J * M];              // attn[b, j, m]
__device__ int   g_topi[B * J * K];
__device__ float g_topw[B * J * K];
__device__ float g_attn_token[B * T * C];        // attn_token[b,t,c]

// ---------------- helpers ---------------------------------------------------
__device__ __forceinline__ void ffma2(unsigned long long &d,
                                      unsigned long long a,
                                      unsigned long long b) {
    asm("fma.rn.f32x2 %0, %1, %2, %0;" : "+l"(d) : "l"(a), "l"(b));
}

union U64F2 { unsigned long long u; float2 f; };

__device__ __forceinline__ float warp_sum(float s) {
    #pragma unroll
    for (int off = 16; off; off >>= 1) s += __shfl_xor_sync(0xffffffffu, s, off);
    return s;
}

__device__ __forceinline__ void cp8(unsigned dst, const float* src) {
    asm volatile("cp.async.ca.shared.global [%0], [%1], 8;\n"
                 :: "r"(dst), "l"(__cvta_generic_to_global(src)) : "memory");
}

// ---------------- K0: zero output + g_attn_token ----------------------------
__global__ void k_zero(float4* __restrict__ out, int n4) {
    int stride = gridDim.x * blockDim.x;
    for (int i = blockIdx.x * blockDim.x + threadIdx.x; i < n4; i += stride)
        out[i] = make_float4(0.f, 0.f, 0.f, 0.f);
    if (blockIdx.x == 0) {
        for (int i = threadIdx.x; i < B * T * C; i += blockDim.x)
            g_attn_token[i] = 0.f;
    }
}

// ---------------- K1: q[b,t,o] = <x[b,t,:], qs_w[t,o,:]> --------------------
// grid 96 = (t, o-chunk of 32). Both batches per block: each qs_w row read once.
__global__ __launch_bounds__(256) void k_q(const float* __restrict__ x,
                                           const float* __restrict__ qs_w) {
    int og = blockIdx.x % 24;
    int t  = blockIdx.x / 24;
    __shared__ float xs[2 * C];
    for (int i = threadIdx.x; i < 2 * C; i += 256) {
        int b = i / C, c = i % C;
        xs[i] = x[((long)b * NTOK + t) * C + c];
    }
    __syncthreads();
    int warp = threadIdx.x >> 5, lane = threadIdx.x & 31;
    #pragma unroll
    for (int oo = 0; oo < 4; oo++) {
        int o = og * 32 + warp * 4 + oo;
        const float* wrow = qs_w + ((long)t * C + o) * C;
        float s0 = 0.f, s1 = 0.f;
        for (int c = lane; c < C; c += 32) {
            float w = wrow[c];
            s0 += xs[c] * w;
            s1 += xs[C + c] * w;
        }
        s0 = warp_sum(s0);
        s1 = warp_sum(s1);
        if (lane == 0) {
            g_q[(0 * T + t) * C + o] = s0;
            g_q[(1 * T + t) * C + o] = s1;
        }
    }
}

// ---------------- K2: qk[b,j,c] = sum_dd q[b,t,h*64+dd] * kv_w[h*64+dd, c] --
// grid 144 = (j, c-chunk of 256). Both batches per block.
__global__ __launch_bounds__(256) void k_qk(const float* __restrict__ kv_w) {
    int ch = blockIdx.x % 3;
    int j  = blockIdx.x / 3;
    int t = j & 3, h = j >> 2;
    __shared__ float qs[2 * D];
    if (threadIdx.x < 2 * D) {
        int b = threadIdx.x >> 6, dd = threadIdx.x & 63;
        qs[threadIdx.x] = g_q[(b * T + t) * C + h * D + dd];
    }
    __syncthreads();
    int c = ch * 256 + threadIdx.x;
    float a0 = 0.f, a1 = 0.f;
    #pragma unroll 8
    for (int dd = 0; dd < D; dd++) {
        float w = kv_w[(long)(h * D + dd) * C + c];
        a0 += qs[dd] * w;
        a1 += qs[D + dd] * w;
    }
    g_qk[((long)(0 * J + j)) * C + c] = a0;
    g_qk[((long)(1 * J + j)) * C + c] = a1;
}

// ---------------- K3: attn[b,j,m] = SCALE * <qk[b,j,:], feature[b,m,:]> -----
// grid (128 m-tiles of 32, B) = 256 blocks -> 2 CTAs/SM, 16 warps/SM.
// Warp w owns q-rows [w*6, w*6+6); lane l owns m-row l of the 32-tile.
// Double-buffered cp.async over 12 c-chunks of 64.
// Stage layout (floats): [qk: 48 x 64][feat: 32 x 66].
#define QK_FL   (48 * 64)              // 3072
#define FSTR    66
#define STAGE_FL (QK_FL + 32 * FSTR)   // 5184 floats = 20736 B/stage
__global__ __launch_bounds__(256) void k_attn(const float* __restrict__ x) {
    extern __shared__ __align__(16) float sm[];   // 2 * STAGE_FL floats
    const int b  = blockIdx.y;
    const int m0 = blockIdx.x * 32;
    const int tid  = threadIdx.x;
    const int warp = tid >> 5;
    const int lane = tid & 31;

    const float* qkb = g_qk + (long)b * J * C;
    const float* xb  = x + ((long)b * NTOK + T + m0) * C;

    // per-thread copy slots: 6 qk float2 + 4 feat float2
    const float* qsrc[6]; unsigned qdst[6];
    #pragma unroll
    for (int u = 0; u < 6; u++) {
        int i = u * 256 + tid;
        int r = i >> 5, cp = i & 31;
        qsrc[u] = qkb + (long)r * C + cp * 2;
        qdst[u] = (unsigned)__cvta_generic_to_shared(&sm[r * 64 + cp * 2]);
    }
    const float* fsrc[4]; unsigned fdst[4];
    #pragma unroll
    for (int u = 0; u < 4; u++) {
        int i = u * 256 + tid;
        int r = i >> 5, cp = i & 31;
        fsrc[u] = xb + (long)r * C + cp * 2;
        fdst[u] = (unsigned)__cvta_generic_to_shared(&sm[QK_FL + r * FSTR + cp * 2]);
    }

    unsigned long long acc[6];
    #pragma unroll
    for (int i = 0; i < 6; i++) acc[i] = 0ull;

    // prefetch chunk 0 into stage 0
    #pragma unroll
    for (int u = 0; u < 6; u++) cp8(qdst[u], qsrc[u]);
    #pragma unroll
    for (int u = 0; u < 4; u++) cp8(fdst[u], fsrc[u]);
    asm volatile("cp.async.commit_group;\n" ::: "memory");

    for (int ic = 0; ic < 12; ic++) {
        if (ic < 11) {
            unsigned so = ((ic + 1) & 1) * (unsigned)(STAGE_FL * 4);
            int cc = (ic + 1) * 64;
            #pragma unroll
            for (int u = 0; u < 6; u++) cp8(qdst[u] + so, qsrc[u] + cc);
            #pragma unroll
            for (int u = 0; u < 4; u++) cp8(fdst[u] + so, fsrc[u] + cc);
            asm volatile("cp.async.commit_group;\n" ::: "memory");
            asm volatile("cp.async.wait_group 1;\n" ::: "memory");
        } else {
            asm volatile("cp.async.wait_group 0;\n" ::: "memory");
        }
        __syncthreads();
        const float* s_qk = sm + (ic & 1) * STAGE_FL;
        const float* s_ft = s_qk + QK_FL;
        #pragma unroll 8
        for (int cp = 0; cp < 32; cp++) {
            unsigned long long f0 =
                *(const unsigned long long*)&s_ft[lane * FSTR + cp * 2];
            #pragma unroll
            for (int i = 0; i < 6; i++) {
                unsigned long long qv =
                    *(const unsigned long long*)&s_qk[(warp * 6 + i) * 64 + cp * 2];
                ffma2(acc[i], qv, f0);
            }
        }
        __syncthreads();
    }
    #pragma unroll
    for (int i = 0; i < 6; i++) {
        int j = warp * 6 + i;
        U64F2 u0; u0.u = acc[i];
        g_attn[((long)(b * J + j)) * M + m0 + lane] = (u0.f.x + u0.f.y) * SCALE;
    }
}

// ---------------- K4: top-2 + softmax per (b,j) row -------------------------
__device__ __forceinline__ bool better(float v, int i, float bv, int bi) {
    return (v > bv) || (v == bv && (unsigned)i < (unsigned)bi);
}
__global__ __launch_bounds__(256) void k_top2() {
    const float* row = g_attn + (long)blockIdx.x * M;
    float v0 = -__int_as_float(0x7f800000), v1 = v0;  // -inf
    int i0 = -1, i1 = -1;
    for (int m = threadIdx.x; m < M; m += 256) {
        float v = row[m];
        if (better(v, m, v0, i0)) { v1 = v0; i1 = i0; v0 = v; i0 = m; }
        else if (better(v, m, v1, i1)) { v1 = v; i1 = m; }
    }
    __shared__ float sv0[256], sv1[256];
    __shared__ int   si0[256], si1[256];
    int tid = threadIdx.x;
    sv0[tid] = v0; si0[tid] = i0;
    sv1[tid] = v1; si1[tid] = i1;
    __syncthreads();
    // tree merge of top-2 sets (all indices distinct across threads)
    #pragma unroll
    for (int s = 128; s >= 1; s >>= 1) {
        if (tid < s) {
            float a0 = sv0[tid], a1 = sv1[tid];
            int   ja = si0[tid], jb = si1[tid];
            float c0 = sv0[tid + s], c1 = sv1[tid + s];
            int   jc = si0[tid + s], jd = si1[tid + s];
            float n0, n1; int m0i, m1i;
            if (better(a0, ja, c0, jc)) {
                n0 = a0; m0i = ja;
                if (better(a1, jb, c0, jc)) { n1 = a1; m1i = jb; }
                else                        { n1 = c0; m1i = jc; }
            } else {
                n0 = c0; m0i = jc;
                if (better(a0, ja, c1, jd)) { n1 = a0; m1i = ja; }
                else                        { n1 = c1; m1i = jd; }
            }
            sv0[tid] = n0; si0[tid] = m0i;
            sv1[tid] = n1; si1[tid] = m1i;
        }
        __syncthreads();
    }
    if (tid == 0) {
        float b0 = sv0[0], b1 = sv1[0];
        float e1 = __expf(b1 - b0);
        float inv = 1.f / (1.f + e1);
        g_topi[blockIdx.x * K + 0] = si0[0];
        g_topi[blockIdx.x * K + 1] = si1[0];
        g_topw[blockIdx.x * K + 0] = inv;
        g_topw[blockIdx.x * K + 1] = e1 * inv;
    }
}

// ---------------- K5: per-selection v projection + expert scatter -----------
// grid 192 = (b, j, k). One selection per block.
__global__ __launch_bounds__(256) void k_select(const float* __restrict__ x,
                                                const float* __restrict__ kv_w,
                                                const float* __restrict__ experts_w,
                                                float* __restrict__ out) {
    int sel = blockIdx.x;
    int k = sel & 1;
    int j = (sel >> 1) % J;
    int b = sel / (2 * J);
    int t = j & 3, h = j >> 2;
    int   m = g_topi[(b * J + j) * K + k];
    float w = g_topw[(b * J + j) * K + k];
    int warp = threadIdx.x >> 5, lane = threadIdx.x & 31;
    __shared__ __align__(16) float feat_sm[C];
    for (int i = threadIdx.x; i < C; i += 256)
        feat_sm[i] = x[((long)b * NTOK + T + m) * C + i];
    __syncthreads();

    // (a) v rows: warp handles dd = warp*8 + i
    #pragma unroll
    for (int i = 0; i < 8; i++) {
        int dd = warp * 8 + i;
        const float* kw = kv_w + (long)(C + h * D + dd) * C;
        float s = 0.f;
        for (int c = lane; c < C; c += 32) s += feat_sm[c] * kw[c];
        s = warp_sum(s);
        if (lane == 0)
            atomicAdd(&g_attn_token[(b * T + t) * C + h * D + dd], w * s);
    }

    // (b) expert projection of the selected feature head-slice
    float4 fa[16];
    const float4* fh4 = (const float4*)(feat_sm + h * D);
    #pragma unroll
    for (int q = 0; q < 16; q++) fa[q] = fh4[q];
    for (int o = threadIdx.x; o < C; o += 256) {
        const float4* ew4 =
            (const float4*)(experts_w + ((long)t * C + o) * C + h * D);
        float s = 0.f;
        #pragma unroll
        for (int q = 0; q < 16; q++) {
            float4 e = ew4[q];
            s += fa[q].x * e.x + fa[q].y * e.y + fa[q].z * e.z + fa[q].w * e.w;
        }
        atomicAdd(&out[((long)b * NTOK + T + m) * C + o], w * s);
    }
}

// ---------------- K6: token_output[b,t,o] = <attn_token[b,t,:], experts_w[t,o,:]>
__global__ __launch_bounds__(256) void k_token(const float* __restrict__ experts_w,
                                               float* __restrict__ out) {
    int og = blockIdx.x % 24;
    int t  = blockIdx.x / 24;
    __shared__ float as[2 * C];
    for (int i = threadIdx.x; i < 2 * C; i += 256) {
        int b = i / C, c = i % C;
        as[i] = g_attn_token[(b * T + t) * C + c];
    }
    __syncthreads();
    int warp = threadIdx.x >> 5, lane = threadIdx.x & 31;
    #pragma unroll
    for (int oo = 0; oo < 4; oo++) {
        int o = og * 32 + warp * 4 + oo;
        const float* wrow = experts_w + ((long)t * C + o) * C;
        float s0 = 0.f, s1 = 0.f;
        for (int c = lane; c < C; c += 32) {
            float w = wrow[c];
            s0 += as[c] * w;
            s1 += as[C + c] * w;
        }
        s0 = warp_sum(s0);
        s1 = warp_sum(s1);
        if (lane == 0) {
            out[((long)0 * NTOK + t) * C + o] = s0;
            out[((long)1 * NTOK + t) * C + o] = s1;
        }
    }
}

// ---------------- launch ----------------------------------------------------
extern "C" void kernel_launch(void* const* d_in, const int* in_sizes, int n_in,
                              void* d_out, int out_size) {
    const float* x         = (const float*)d_in[0];
    const float* qs_w      = (const float*)d_in[1];
    const float* kv_w      = (const float*)d_in[2];
    const float* experts_w = (const float*)d_in[3];
    float* out = (float*)d_out;

    k_zero<<<1536, 256>>>((float4*)out, out_size / 4);
    k_q<<<96, 256>>>(x, qs_w);
    k_qk<<<144, 256>>>(kv_w);
    k_attn<<<dim3(128, B), 256, 2 * STAGE_FL * 4>>>(x);
    k_top2<<<B * J, 256>>>();
    k_select<<<192, 256>>>(x, kv_w, experts_w, out);
    k_token<<<96, 256>>>(experts_w, out);
}

// round 6
// speedup vs baseline: 1.6306x; 1.0305x over previous
#include <cuda_runtime.h>
#include <cuda_bf16.h>

// Problem constants
#define B   2
#define NTOK 4100
#define C   768
#define T   4
#define H   12
#define D   64
#define K   2
#define M   4096          // NTOK - T
#define J   48            // H*T query rows per batch
#define SCALE 0.125f      // d^-0.5

// ---------------- scratch (device globals; no allocations allowed) ----------
__device__ float g_q[B * T * C];                 // q[b,t,o]
__device__ float g_qk[B * J * C];                // qk[b, h*4+t, c]
__device__ float g_attn2[2][B * J * M];          // c-split partial attn
__device__ int   g_topi[B * J * K];
__device__ float g_topw[B * J * K];
__device__ float g_attn_token[B * T * C];        // attn_token[b,t,c]

// ---------------- helpers ---------------------------------------------------
__device__ __forceinline__ void ffma2(unsigned long long &d,
                                      unsigned long long a,
                                      unsigned long long b) {
    asm("fma.rn.f32x2 %0, %1, %2, %0;" : "+l"(d) : "l"(a), "l"(b));
}

union U64F2 { unsigned long long u; float2 f; };

__device__ __forceinline__ float warp_sum(float s) {
    #pragma unroll
    for (int off = 16; off; off >>= 1) s += __shfl_xor_sync(0xffffffffu, s, off);
    return s;
}

__device__ __forceinline__ void cp8(unsigned dst, const float* src) {
    asm volatile("cp.async.ca.shared.global [%0], [%1], 8;\n"
                 :: "r"(dst), "l"(__cvta_generic_to_global(src)) : "memory");
}

// ---------------- K0: zero output -------------------------------------------
__global__ void k_zero(float4* __restrict__ out, int n4) {
    int stride = gridDim.x * blockDim.x;
    for (int i = blockIdx.x * blockDim.x + threadIdx.x; i < n4; i += stride)
        out[i] = make_float4(0.f, 0.f, 0.f, 0.f);
}

// ---------------- K1: q[b,t,o] = <x[b,t,:], qs_w[t,o,:]> --------------------
// grid 96 = (t, o-chunk of 32). Both batches per block.
__global__ __launch_bounds__(256) void k_q(const float* __restrict__ x,
                                           const float* __restrict__ qs_w) {
    int og = blockIdx.x % 24;
    int t  = blockIdx.x / 24;
    __shared__ float xs[2 * C];
    for (int i = threadIdx.x; i < 2 * C; i += 256) {
        int b = i / C, c = i % C;
        xs[i] = x[((long)b * NTOK + t) * C + c];
    }
    __syncthreads();
    int warp = threadIdx.x >> 5, lane = threadIdx.x & 31;
    #pragma unroll
    for (int oo = 0; oo < 4; oo++) {
        int o = og * 32 + warp * 4 + oo;
        const float* wrow = qs_w + ((long)t * C + o) * C;
        float s0 = 0.f, s1 = 0.f;
        for (int c = lane; c < C; c += 32) {
            float w = wrow[c];
            s0 += xs[c] * w;
            s1 += xs[C + c] * w;
        }
        s0 = warp_sum(s0);
        s1 = warp_sum(s1);
        if (lane == 0) {
            g_q[(0 * T + t) * C + o] = s0;
            g_q[(1 * T + t) * C + o] = s1;
        }
    }
}

// ---------------- K2: qk[b,j,c] = sum_dd q[b,t,h*64+dd] * kv_w[h*64+dd, c] --
// grid 144 = (j, c-chunk of 256). Both batches per block.
__global__ __launch_bounds__(256) void k_qk(const float* __restrict__ kv_w) {
    int ch = blockIdx.x % 3;
    int j  = blockIdx.x / 3;
    int t = j & 3, h = j >> 2;
    __shared__ float qs[2 * D];
    if (threadIdx.x < 2 * D) {
        int b = threadIdx.x >> 6, dd = threadIdx.x & 63;
        qs[threadIdx.x] = g_q[(b * T + t) * C + h * D + dd];
    }
    __syncthreads();
    int c = ch * 256 + threadIdx.x;
    float a0 = 0.f, a1 = 0.f;
    #pragma unroll 8
    for (int dd = 0; dd < D; dd++) {
        float w = kv_w[(long)(h * D + dd) * C + c];
        a0 += qs[dd] * w;
        a1 += qs[D + dd] * w;
    }
    g_qk[((long)(0 * J + j)) * C + c] = a0;
    g_qk[((long)(1 * J + j)) * C + c] = a1;
}

// ---------------- K3: partial attn over a c-half ----------------------------
// grid (64 m-tiles, B, 2 c-halves) = 256 CTAs -> 2 CTAs/SM, 16 warps/SM.
// Warp w owns q-rows [w*6,w*6+6); lane owns m {lane, lane+32}. 6 chunks of 64 c.
// Copy geometry: row r = u*8 + warp, pair index = lane (constant strides).
#define QK_FL   (48 * 64)              // 3072
#define FSTR    66
#define STAGE_FL (QK_FL + 64 * FSTR)   // 7296 floats = 29184 B/stage
__global__ __launch_bounds__(256, 2) void k_attn(const float* __restrict__ x) {
    extern __shared__ __align__(16) float sm[];   // 2 * STAGE_FL floats
    const int b  = blockIdx.y;
    const int m0 = blockIdx.x * 64;
    const int cs = blockIdx.z;
    const int tid  = threadIdx.x;
    const int warp = tid >> 5;
    const int lane = tid & 31;

    const float* qsrc0 = g_qk + (long)b * J * C + cs * 384
                       + (long)warp * C + lane * 2;              // +u*8*C
    const float* fsrc0 = x + ((long)b * NTOK + T + m0) * C + cs * 384
                       + (long)warp * C + lane * 2;              // +u*8*C
    unsigned qdst0 = (unsigned)__cvta_generic_to_shared(&sm[warp * 64 + lane * 2]);
    unsigned fdst0 = (unsigned)__cvta_generic_to_shared(
                         &sm[QK_FL + warp * FSTR + lane * 2]);

    unsigned long long acc[6][2];
    #pragma unroll
    for (int i = 0; i < 6; i++) { acc[i][0] = 0ull; acc[i][1] = 0ull; }

    // prefetch chunk 0 into stage 0
    #pragma unroll
    for (int u = 0; u < 6; u++) cp8(qdst0 + u * 2048, qsrc0 + u * 8 * C);
    #pragma unroll
    for (int u = 0; u < 8; u++) cp8(fdst0 + u * 2112, fsrc0 + u * 8 * C);
    asm volatile("cp.async.commit_group;\n" ::: "memory");

    for (int ic = 0; ic < 6; ic++) {
        if (ic < 5) {
            unsigned so = ((ic + 1) & 1) * (unsigned)(STAGE_FL * 4);
            int cc = (ic + 1) * 64;
            #pragma unroll
            for (int u = 0; u < 6; u++)
                cp8(qdst0 + so + u * 2048, qsrc0 + cc + u * 8 * C);
            #pragma unroll
            for (int u = 0; u < 8; u++)
                cp8(fdst0 + so + u * 2112, fsrc0 + cc + u * 8 * C);
            asm volatile("cp.async.commit_group;\n" ::: "memory");
            asm volatile("cp.async.wait_group 1;\n" ::: "memory");
        } else {
            asm volatile("cp.async.wait_group 0;\n" ::: "memory");
        }
        __syncthreads();
        const float* s_qk = sm + (ic & 1) * STAGE_FL;
        const float* s_ft = s_qk + QK_FL;
        #pragma unroll 8
        for (int cp = 0; cp < 32; cp++) {
            unsigned long long f0 =
                *(const unsigned long long*)&s_ft[lane * FSTR + cp * 2];
            unsigned long long f1 =
                *(const unsigned long long*)&s_ft[(lane + 32) * FSTR + cp * 2];
            #pragma unroll
            for (int i = 0; i < 6; i++) {
                unsigned long long qv =
                    *(const unsigned long long*)&s_qk[(warp * 6 + i) * 64 + cp * 2];
                ffma2(acc[i][0], qv, f0);
                ffma2(acc[i][1], qv, f1);
            }
        }
        __syncthreads();
    }
    #pragma unroll
    for (int i = 0; i < 6; i++) {
        int j = warp * 6 + i;
        float* row = g_attn2[cs] + ((long)(b * J + j)) * M + m0;
        U64F2 u0; u0.u = acc[i][0];
        U64F2 u1; u1.u = acc[i][1];
        row[lane]      = (u0.f.x + u0.f.y) * SCALE;
        row[lane + 32] = (u1.f.x + u1.f.y) * SCALE;
    }
}

// ---------------- K4: top-2 + softmax per (b,j) row (adds c-split halves) ---
__device__ __forceinline__ bool better(float v, int i, float bv, int bi) {
    return (v > bv) || (v == bv && (unsigned)i < (unsigned)bi);
}
__global__ __launch_bounds__(256) void k_top2() {
    const float* r0 = g_attn2[0] + (long)blockIdx.x * M;
    const float* r1 = g_attn2[1] + (long)blockIdx.x * M;
    float v0 = -__int_as_float(0x7f800000), v1 = v0;  // -inf
    int i0 = -1, i1 = -1;
    for (int m = threadIdx.x; m < M; m += 256) {
        float v = r0[m] + r1[m];
        if (better(v, m, v0, i0)) { v1 = v0; i1 = i0; v0 = v; i0 = m; }
        else if (better(v, m, v1, i1)) { v1 = v; i1 = m; }
    }
    __shared__ float sv0[256], sv1[256];
    __shared__ int   si0[256], si1[256];
    int tid = threadIdx.x;
    sv0[tid] = v0; si0[tid] = i0;
    sv1[tid] = v1; si1[tid] = i1;
    __syncthreads();
    #pragma unroll
    for (int s = 128; s >= 1; s >>= 1) {
        if (tid < s) {
            float a0 = sv0[tid], a1 = sv1[tid];
            int   ja = si0[tid], jb = si1[tid];
            float c0 = sv0[tid + s], c1 = sv1[tid + s];
            int   jc = si0[tid + s], jd = si1[tid + s];
            float n0, n1; int m0i, m1i;
            if (better(a0, ja, c0, jc)) {
                n0 = a0; m0i = ja;
                if (better(a1, jb, c0, jc)) { n1 = a1; m1i = jb; }
                else                        { n1 = c0; m1i = jc; }
            } else {
                n0 = c0; m0i = jc;
                if (better(a0, ja, c1, jd)) { n1 = a0; m1i = ja; }
                else                        { n1 = c1; m1i = jd; }
            }
            sv0[tid] = n0; si0[tid] = m0i;
            sv1[tid] = n1; si1[tid] = m1i;
        }
        __syncthreads();
    }
    if (tid == 0) {
        float b0 = sv0[0], b1 = sv1[0];
        float e1 = __expf(b1 - b0);
        float inv = 1.f / (1.f + e1);
        g_topi[blockIdx.x * K + 0] = si0[0];
        g_topi[blockIdx.x * K + 1] = si1[0];
        g_topw[blockIdx.x * K + 0] = inv;
        g_topw[blockIdx.x * K + 1] = e1 * inv;
    }
}

// ---------------- K5: both selections of (b,j) in one block -----------------
// grid 96 = (b,j). Weight slices (kv_w v-rows, experts head slice) read ONCE.
//   g_attn_token[b,t,h*64+dd] = w0*<f0,kw> + w1*<f1,kw>   (exclusive write)
//   out[b, 4+m_k, o]         += w_k * <f_k[h*64:+64], experts_w[t,o,h*64:+64]>
__global__ __launch_bounds__(256) void k_select(const float* __restrict__ x,
                                                const float* __restrict__ kv_w,
                                                const float* __restrict__ experts_w,
                                                float* __restrict__ out) {
    int b = blockIdx.x / J;
    int j = blockIdx.x % J;
    int t = j & 3, h = j >> 2;
    int   m0 = g_topi[(b * J + j) * K + 0];
    int   m1 = g_topi[(b * J + j) * K + 1];
    float w0 = g_topw[(b * J + j) * K + 0];
    float w1 = g_topw[(b * J + j) * K + 1];
    int warp = threadIdx.x >> 5, lane = threadIdx.x & 31;
    __shared__ __align__(16) float f0s[C], f1s[C];
    for (int i = threadIdx.x; i < C; i += 256) {
        f0s[i] = x[((long)b * NTOK + T + m0) * C + i];
        f1s[i] = x[((long)b * NTOK + T + m1) * C + i];
    }
    __syncthreads();

    // (a) v rows: warp handles dd = warp*8 + i; single kv_w pass for both k
    #pragma unroll
    for (int i = 0; i < 8; i++) {
        int dd = warp * 8 + i;
        const float* kw = kv_w + (long)(C + h * D + dd) * C;
        float s0 = 0.f, s1 = 0.f;
        for (int c = lane; c < C; c += 32) {
            float w = kw[c];
            s0 += f0s[c] * w;
            s1 += f1s[c] * w;
        }
        s0 = warp_sum(s0);
        s1 = warp_sum(s1);
        if (lane == 0)
            g_attn_token[(b * T + t) * C + h * D + dd] = w0 * s0 + w1 * s1;
    }

    // (b) expert projection: warps 0-3 -> k=0, warps 4-7 -> k=1
    int kk = warp >> 2;
    const float* fs = kk ? f1s : f0s;
    int   m = kk ? m1 : m0;
    float w = kk ? w1 : w0;
    float4 fa[16];
    const float4* fh4 = (const float4*)(fs + h * D);
    #pragma unroll
    for (int q = 0; q < 16; q++) fa[q] = fh4[q];
    int wtid = (warp & 3) * 32 + lane;  // 0..127
    for (int o = wtid; o < C; o += 128) {
        const float4* ew4 =
            (const float4*)(experts_w + ((long)t * C + o) * C + h * D);
        float s = 0.f;
        #pragma unroll
        for (int q = 0; q < 16; q++) {
            float4 e = ew4[q];
            s += fa[q].x * e.x + fa[q].y * e.y + fa[q].z * e.z + fa[q].w * e.w;
        }
        atomicAdd(&out[((long)b * NTOK + T + m) * C + o], w * s);
    }
}

// ---------------- K6: token_output[b,t,o] = <attn_token[b,t,:], experts_w[t,o,:]>
__global__ __launch_bounds__(256) void k_token(const float* __restrict__ experts_w,
                                               float* __restrict__ out) {
    int og = blockIdx.x % 24;
    int t  = blockIdx.x / 24;
    __shared__ float as[2 * C];
    for (int i = threadIdx.x; i < 2 * C; i += 256) {
        int b = i / C, c = i % C;
        as[i] = g_attn_token[(b * T + t) * C + c];
    }
    __syncthreads();
    int warp = threadIdx.x >> 5, lane = threadIdx.x & 31;
    #pragma unroll
    for (int oo = 0; oo < 4; oo++) {
        int o = og * 32 + warp * 4 + oo;
        const float* wrow = experts_w + ((long)t * C + o) * C;
        float s0 = 0.f, s1 = 0.f;
        for (int c = lane; c < C; c += 32) {
            float w = wrow[c];
            s0 += as[c] * w;
            s1 += as[C + c] * w;
        }
        s0 = warp_sum(s0);
        s1 = warp_sum(s1);
        if (lane == 0) {
            out[((long)0 * NTOK + t) * C + o] = s0;
            out[((long)1 * NTOK + t) * C + o] = s1;
        }
    }
}

// ---------------- launch ----------------------------------------------------
extern "C" void kernel_launch(void* const* d_in, const int* in_sizes, int n_in,
                              void* d_out, int out_size) {
    const float* x         = (const float*)d_in[0];
    const float* qs_w      = (const float*)d_in[1];
    const float* kv_w      = (const float*)d_in[2];
    const float* experts_w = (const float*)d_in[3];
    float* out = (float*)d_out;

    cudaFuncSetAttribute(k_attn, cudaFuncAttributeMaxDynamicSharedMemorySize,
                         2 * STAGE_FL * 4);

    k_zero<<<1536, 256>>>((float4*)out, out_size / 4);
    k_q<<<96, 256>>>(x, qs_w);
    k_qk<<<144, 256>>>(kv_w);
    k_attn<<<dim3(64, B, 2), 256, 2 * STAGE_FL * 4>>>(x);
    k_top2<<<B * J, 256>>>();
    k_select<<<96, 256>>>(x, kv_w, experts_w, out);
    k_token<<<96, 256>>>(experts_w, out);
}

// round 7
// speedup vs baseline: 1.7888x; 1.0970x over previous
#include <cuda_runtime.h>
#include <cuda_bf16.h>

// Problem constants
#define B   2
#define NTOK 4100
#define C   768
#define T   4
#define H   12
#define D   64
#define K   2
#define M   4096          // NTOK - T
#define J   48            // H*T query rows per batch
#define SCALE 0.125f      // d^-0.5

#define CSP  4            // c-splits for k_attn
#define CPER (C / CSP)    // 192 channels per split

// ---------------- scratch (device globals; no allocations allowed) ----------
__device__ float g_q[B * T * C];                 // q[b,t,o]
__device__ float g_qk[B * J * C];                // qk[b, h*4+t, c]
__device__ float g_attn2[CSP][B * J * M];        // c-split partial attn
__device__ int   g_topi[B * J * K];
__device__ float g_topw[B * J * K];
__device__ float g_attn_token[B * T * C];        // attn_token[b,t,c]

// ---------------- helpers ---------------------------------------------------
__device__ __forceinline__ void ffma2(unsigned long long &d,
                                      unsigned long long a,
                                      unsigned long long b) {
    asm("fma.rn.f32x2 %0, %1, %2, %0;" : "+l"(d) : "l"(a), "l"(b));
}

union U64F2 { unsigned long long u; float2 f; };

__device__ __forceinline__ float warp_sum(float s) {
    #pragma unroll
    for (int off = 16; off; off >>= 1) s += __shfl_xor_sync(0xffffffffu, s, off);
    return s;
}

__device__ __forceinline__ void cp8(unsigned dst, const float* src) {
    asm volatile("cp.async.ca.shared.global [%0], [%1], 8;\n"
                 :: "r"(dst), "l"(__cvta_generic_to_global(src)) : "memory");
}

// ---------------- K1: q[b,t,o] = <x[b,t,:], qs_w[t,o,:]> --------------------
// grid 384 = (t, o-group of 8). One output per warp, both batches.
__global__ __launch_bounds__(256) void k_q(const float* __restrict__ x,
                                           const float* __restrict__ qs_w) {
    int og = blockIdx.x % 96;
    int t  = blockIdx.x / 96;
    __shared__ float xs[2 * C];
    for (int i = threadIdx.x; i < 2 * C; i += 256) {
        int b = i / C, c = i % C;
        xs[i] = x[((long)b * NTOK + t) * C + c];
    }
    __syncthreads();
    int warp = threadIdx.x >> 5, lane = threadIdx.x & 31;
    int o = og * 8 + warp;
    const float* wrow = qs_w + ((long)t * C + o) * C;
    float s0 = 0.f, s1 = 0.f;
    #pragma unroll 8
    for (int c = lane; c < C; c += 32) {
        float w = wrow[c];
        s0 += xs[c] * w;
        s1 += xs[C + c] * w;
    }
    s0 = warp_sum(s0);
    s1 = warp_sum(s1);
    if (lane == 0) {
        g_q[(0 * T + t) * C + o] = s0;
        g_q[(1 * T + t) * C + o] = s1;
    }
}

// ---------------- K2: qk[b,j,c] = sum_dd q[b,t,h*64+dd] * kv_w[h*64+dd, c] --
// grid 288 = (j, c-chunk of 128), 128 threads. Both batches per block.
__global__ __launch_bounds__(128) void k_qk(const float* __restrict__ kv_w) {
    int ch = blockIdx.x % 6;
    int j  = blockIdx.x / 6;
    int t = j & 3, h = j >> 2;
    __shared__ float qs[2 * D];
    {
        int b = threadIdx.x >> 6, dd = threadIdx.x & 63;
        qs[threadIdx.x] = g_q[(b * T + t) * C + h * D + dd];
    }
    __syncthreads();
    int c = ch * 128 + threadIdx.x;
    float a0 = 0.f, a1 = 0.f;
    #pragma unroll 8
    for (int dd = 0; dd < D; dd++) {
        float w = kv_w[(long)(h * D + dd) * C + c];
        a0 += qs[dd] * w;
        a1 += qs[D + dd] * w;
    }
    g_qk[((long)(0 * J + j)) * C + c] = a0;
    g_qk[((long)(1 * J + j)) * C + c] = a1;
}

// ---------------- K3: partial attn over a c-quarter -------------------------
// grid (64 m-tiles, B, 4 c-quarters) = 512 CTAs, occ 4 -> ~28 warps/SM.
// Warp w owns q-rows [w*6,w*6+6); lane owns m {lane, lane+32}.
// 6 chunks of 32 c, double-buffered cp.async.
// Stage (floats): [qk: 48 x 32][feat: 64 x 34].
#define CHUNK 32
#define NCH   (CPER / CHUNK)           // 6
#define QK_FL (48 * CHUNK)             // 1536
#define FSTR  34
#define STAGE_FL (QK_FL + 64 * FSTR)   // 3712 floats = 14848 B/stage
__global__ __launch_bounds__(256, 4) void k_attn(const float* __restrict__ x) {
    extern __shared__ __align__(16) float sm[];   // 2 * STAGE_FL floats
    const int b  = blockIdx.y;
    const int m0 = blockIdx.x * 64;
    const int cs = blockIdx.z;
    const int tid  = threadIdx.x;
    const int warp = tid >> 5;
    const int lane = tid & 31;
    const int cr = tid >> 4;      // copy row base 0..15
    const int cp0 = tid & 15;     // copy pair    0..15

    const float* qsrc0 = g_qk + (long)b * J * C + cs * CPER
                       + (long)cr * C + cp0 * 2;               // +u*16*C
    const float* fsrc0 = x + ((long)b * NTOK + T + m0) * C + cs * CPER
                       + (long)cr * C + cp0 * 2;               // +u*16*C
    unsigned qdst0 = (unsigned)__cvta_generic_to_shared(
                         &sm[cr * CHUNK + cp0 * 2]);           // +u*2048B
    unsigned fdst0 = (unsigned)__cvta_generic_to_shared(
                         &sm[QK_FL + cr * FSTR + cp0 * 2]);    // +u*2176B

    unsigned long long acc[6][2];
    #pragma unroll
    for (int i = 0; i < 6; i++) { acc[i][0] = 0ull; acc[i][1] = 0ull; }

    // prefetch chunk 0 into stage 0
    #pragma unroll
    for (int u = 0; u < 3; u++) cp8(qdst0 + u * 2048, qsrc0 + u * 16 * C);
    #pragma unroll
    for (int u = 0; u < 4; u++) cp8(fdst0 + u * 2176, fsrc0 + u * 16 * C);
    asm volatile("cp.async.commit_group;\n" ::: "memory");

    for (int ic = 0; ic < NCH; ic++) {
        if (ic < NCH - 1) {
            unsigned so = ((ic + 1) & 1) * (unsigned)(STAGE_FL * 4);
            int cc = (ic + 1) * CHUNK;
            #pragma unroll
            for (int u = 0; u < 3; u++)
                cp8(qdst0 + so + u * 2048, qsrc0 + cc + u * 16 * C);
            #pragma unroll
            for (int u = 0; u < 4; u++)
                cp8(fdst0 + so + u * 2176, fsrc0 + cc + u * 16 * C);
            asm volatile("cp.async.commit_group;\n" ::: "memory");
            asm volatile("cp.async.wait_group 1;\n" ::: "memory");
        } else {
            asm volatile("cp.async.wait_group 0;\n" ::: "memory");
        }
        __syncthreads();
        const float* s_qk = sm + (ic & 1) * STAGE_FL;
        const float* s_ft = s_qk + QK_FL;
        #pragma unroll
        for (int cp = 0; cp < 16; cp++) {
            unsigned long long f0 =
                *(const unsigned long long*)&s_ft[lane * FSTR + cp * 2];
            unsigned long long f1 =
                *(const unsigned long long*)&s_ft[(lane + 32) * FSTR + cp * 2];
            #pragma unroll
            for (int i = 0; i < 6; i++) {
                unsigned long long qv =
                    *(const unsigned long long*)&s_qk[(warp * 6 + i) * CHUNK + cp * 2];
                ffma2(acc[i][0], qv, f0);
                ffma2(acc[i][1], qv, f1);
            }
        }
        __syncthreads();
    }
    #pragma unroll
    for (int i = 0; i < 6; i++) {
        int j = warp * 6 + i;
        float* row = g_attn2[cs] + ((long)(b * J + j)) * M + m0;
        U64F2 u0; u0.u = acc[i][0];
        U64F2 u1; u1.u = acc[i][1];
        row[lane]      = (u0.f.x + u0.f.y) * SCALE;
        row[lane + 32] = (u1.f.x + u1.f.y) * SCALE;
    }
}

// ---------------- K4: top-2 + softmax per (b,j) row (adds 4 c-partials) -----
__device__ __forceinline__ bool better(float v, int i, float bv, int bi) {
    return (v > bv) || (v == bv && (unsigned)i < (unsigned)bi);
}
__global__ __launch_bounds__(256) void k_top2() {
    const float* r0 = g_attn2[0] + (long)blockIdx.x * M;
    const float* r1 = g_attn2[1] + (long)blockIdx.x * M;
    const float* r2 = g_attn2[2] + (long)blockIdx.x * M;
    const float* r3 = g_attn2[3] + (long)blockIdx.x * M;
    float v0 = -__int_as_float(0x7f800000), v1 = v0;  // -inf
    int i0 = -1, i1 = -1;
    for (int m = threadIdx.x; m < M; m += 256) {
        float v = (r0[m] + r1[m]) + (r2[m] + r3[m]);
        if (better(v, m, v0, i0)) { v1 = v0; i1 = i0; v0 = v; i0 = m; }
        else if (better(v, m, v1, i1)) { v1 = v; i1 = m; }
    }
    __shared__ float sv0[256], sv1[256];
    __shared__ int   si0[256], si1[256];
    int tid = threadIdx.x;
    sv0[tid] = v0; si0[tid] = i0;
    sv1[tid] = v1; si1[tid] = i1;
    __syncthreads();
    #pragma unroll
    for (int s = 128; s >= 1; s >>= 1) {
        if (tid < s) {
            float a0 = sv0[tid], a1 = sv1[tid];
            int   ja = si0[tid], jb = si1[tid];
            float c0 = sv0[tid + s], c1 = sv1[tid + s];
            int   jc = si0[tid + s], jd = si1[tid + s];
            float n0, n1; int m0i, m1i;
            if (better(a0, ja, c0, jc)) {
                n0 = a0; m0i = ja;
                if (better(a1, jb, c0, jc)) { n1 = a1; m1i = jb; }
                else                        { n1 = c0; m1i = jc; }
            } else {
                n0 = c0; m0i = jc;
                if (better(a0, ja, c1, jd)) { n1 = a0; m1i = ja; }
                else                        { n1 = c1; m1i = jd; }
            }
            sv0[tid] = n0; si0[tid] = m0i;
            sv1[tid] = n1; si1[tid] = m1i;
        }
        __syncthreads();
    }
    if (tid == 0) {
        float b0 = sv0[0], b1 = sv1[0];
        float e1 = __expf(b1 - b0);
        float inv = 1.f / (1.f + e1);
        g_topi[blockIdx.x * K + 0] = si0[0];
        g_topi[blockIdx.x * K + 1] = si1[0];
        g_topw[blockIdx.x * K + 0] = inv;
        g_topw[blockIdx.x * K + 1] = e1 * inv;
    }
}

// ---------------- K5: both selections of (b,j) in one block -----------------
// grid 96 = (b,j). kv_w v-rows / experts head slice read ONCE per block.
// Part (a) is loop-interchanged: 8 kw rows live per c-iteration (MLP 8).
__global__ __launch_bounds__(256) void k_select(const float* __restrict__ x,
                                                const float* __restrict__ kv_w,
                                                const float* __restrict__ experts_w,
                                                float* __restrict__ out) {
    int b = blockIdx.x / J;
    int j = blockIdx.x % J;
    int t = j & 3, h = j >> 2;
    int   m0 = g_topi[(b * J + j) * K + 0];
    int   m1 = g_topi[(b * J + j) * K + 1];
    float w0 = g_topw[(b * J + j) * K + 0];
    float w1 = g_topw[(b * J + j) * K + 1];
    int warp = threadIdx.x >> 5, lane = threadIdx.x & 31;
    __shared__ __align__(16) float f0s[C], f1s[C];
    for (int i = threadIdx.x; i < C; i += 256) {
        f0s[i] = x[((long)b * NTOK + T + m0) * C + i];
        f1s[i] = x[((long)b * NTOK + T + m1) * C + i];
    }
    __syncthreads();

    // (a) v rows dd = warp*8 + i, all 8 rows accumulated in one c-pass
    {
        const float* kw = kv_w + (long)(C + h * D + warp * 8) * C;
        float a0[8], a1[8];
        #pragma unroll
        for (int i = 0; i < 8; i++) { a0[i] = 0.f; a1[i] = 0.f; }
        #pragma unroll 2
        for (int c = lane; c < C; c += 32) {
            float f0 = f0s[c], f1 = f1s[c];
            #pragma unroll
            for (int i = 0; i < 8; i++) {
                float w = kw[(long)i * C + c];
                a0[i] += f0 * w;
                a1[i] += f1 * w;
            }
        }
        #pragma unroll
        for (int i = 0; i < 8; i++) {
            float s0 = warp_sum(a0[i]);
            float s1 = warp_sum(a1[i]);
            if (lane == 0)
                g_attn_token[(b * T + t) * C + h * D + warp * 8 + i] =
                    w0 * s0 + w1 * s1;
        }
    }

    // (b) expert projection: warps 0-3 -> k=0, warps 4-7 -> k=1
    int kk = warp >> 2;
    const float* fs = kk ? f1s : f0s;
    int   m = kk ? m1 : m0;
    float w = kk ? w1 : w0;
    float4 fa[16];
    const float4* fh4 = (const float4*)(fs + h * D);
    #pragma unroll
    for (int q = 0; q < 16; q++) fa[q] = fh4[q];
    int wtid = (warp & 3) * 32 + lane;  // 0..127
    for (int o = wtid; o < C; o += 128) {
        const float4* ew4 =
            (const float4*)(experts_w + ((long)t * C + o) * C + h * D);
        float s = 0.f;
        #pragma unroll
        for (int q = 0; q < 16; q++) {
            float4 e = ew4[q];
            s += fa[q].x * e.x + fa[q].y * e.y + fa[q].z * e.z + fa[q].w * e.w;
        }
        atomicAdd(&out[((long)b * NTOK + T + m) * C + o], w * s);
    }
}

// ---------------- K6: token_output[b,t,o] = <attn_token[b,t,:], experts_w[t,o,:]>
__global__ __launch_bounds__(256) void k_token(const float* __restrict__ experts_w,
                                               float* __restrict__ out) {
    int og = blockIdx.x % 96;
    int t  = blockIdx.x / 96;
    __shared__ float as[2 * C];
    for (int i = threadIdx.x; i < 2 * C; i += 256) {
        int b = i / C, c = i % C;
        as[i] = g_attn_token[(b * T + t) * C + c];
    }
    __syncthreads();
    int warp = threadIdx.x >> 5, lane = threadIdx.x & 31;
    int o = og * 8 + warp;
    const float* wrow = experts_w + ((long)t * C + o) * C;
    float s0 = 0.f, s1 = 0.f;
    #pragma unroll 8
    for (int c = lane; c < C; c += 32) {
        float w = wrow[c];
        s0 += as[c] * w;
        s1 += as[C + c] * w;
    }
    s0 = warp_sum(s0);
    s1 = warp_sum(s1);
    if (lane == 0) {
        out[((long)0 * NTOK + t) * C + o] = s0;
        out[((long)1 * NTOK + t) * C + o] = s1;
    }
}

// ---------------- launch ----------------------------------------------------
extern "C" void kernel_launch(void* const* d_in, const int* in_sizes, int n_in,
                              void* d_out, int out_size) {
    const float* x         = (const float*)d_in[0];
    const float* qs_w      = (const float*)d_in[1];
    const float* kv_w      = (const float*)d_in[2];
    const float* experts_w = (const float*)d_in[3];
    float* out = (float*)d_out;

    cudaMemsetAsync(out, 0, (size_t)out_size * sizeof(float));
    k_q<<<384, 256>>>(x, qs_w);
    k_qk<<<288, 128>>>(kv_w);
    k_attn<<<dim3(64, B, CSP), 256, 2 * STAGE_FL * 4>>>(x);
    k_top2<<<B * J, 256>>>();
    k_select<<<96, 256>>>(x, kv_w, experts_w, out);
    k_token<<<384, 256>>>(experts_w, out);
}

// round 9
// speedup vs baseline: 1.8967x; 1.0603x over previous
#include <cuda_runtime.h>
#include <cuda_bf16.h>

// Problem constants
#define B   2
#define NTOK 4100
#define C   768
#define T   4
#define H   12
#define D   64
#define K   2
#define M   4096          // NTOK - T
#define J   48            // H*T query rows per batch
#define SCALE 0.125f      // d^-0.5

#define CSP  4            // c-splits for k_attn
#define CPER (C / CSP)    // 192 channels per split
#define MT   8            // m-tiles for two-stage top2
#define MTS  (M / MT)     // 512 elements per tile

// ---------------- scratch (device globals; no allocations allowed) ----------
__device__ float g_q[B * T * C];                 // q[b,t,o]
__device__ float g_qk[B * J * C];                // qk[b, h*4+t, c]
__device__ float g_attn2[CSP][B * J * M];        // c-split partial attn
__device__ float g_cv[B * J][MT][2];             // stage-1 top2 candidates (val)
__device__ int   g_ci[B * J][MT][2];             // stage-1 top2 candidates (idx)
__device__ int   g_topi[B * J * K];
__device__ float g_topw[B * J * K];
__device__ float g_attn_token[B * T * C];        // attn_token[b,t,c]

// ---------------- helpers ---------------------------------------------------
__device__ __forceinline__ void ffma2(unsigned long long &d,
                                      unsigned long long a,
                                      unsigned long long b) {
    asm("fma.rn.f32x2 %0, %1, %2, %0;" : "+l"(d) : "l"(a), "l"(b));
}

union U64F2 { unsigned long long u; float2 f; };

__device__ __forceinline__ float warp_sum(float s) {
    #pragma unroll
    for (int off = 16; off; off >>= 1) s += __shfl_xor_sync(0xffffffffu, s, off);
    return s;
}

__device__ __forceinline__ void cp8(unsigned dst, const float* src) {
    asm volatile("cp.async.ca.shared.global [%0], [%1], 8;\n"
                 :: "r"(dst), "l"(__cvta_generic_to_global(src)) : "memory");
}

// ---------------- K1: q[b,t,o] = <x[b,t,:], qs_w[t,o,:]> --------------------
// grid 384 = (t, o-group of 8). One output per warp, both batches.
__global__ __launch_bounds__(256) void k_q(const float* __restrict__ x,
                                           const float* __restrict__ qs_w) {
    int og = blockIdx.x % 96;
    int t  = blockIdx.x / 96;
    __shared__ float xs[2 * C];
    for (int i = threadIdx.x; i < 2 * C; i += 256) {
        int b = i / C, c = i % C;
        xs[i] = x[((long)b * NTOK + t) * C + c];
    }
    __syncthreads();
    int warp = threadIdx.x >> 5, lane = threadIdx.x & 31;
    int o = og * 8 + warp;
    const float* wrow = qs_w + ((long)t * C + o) * C;
    float s0 = 0.f, s1 = 0.f;
    #pragma unroll 8
    for (int c = lane; c < C; c += 32) {
        float w = wrow[c];
        s0 += xs[c] * w;
        s1 += xs[C + c] * w;
    }
    s0 = warp_sum(s0);
    s1 = warp_sum(s1);
    if (lane == 0) {
        g_q[(0 * T + t) * C + o] = s0;
        g_q[(1 * T + t) * C + o] = s1;
    }
}

// ---------------- K2: qk[b,j,c] = sum_dd q[b,t,h*64+dd] * kv_w[h*64+dd, c] --
// grid 288 = (j, c-chunk of 128), 128 threads. Both batches per block.
__global__ __launch_bounds__(128) void k_qk(const float* __restrict__ kv_w) {
    int ch = blockIdx.x % 6;
    int j  = blockIdx.x / 6;
    int t = j & 3, h = j >> 2;
    __shared__ float qs[2 * D];
    {
        int b = threadIdx.x >> 6, dd = threadIdx.x & 63;
        qs[threadIdx.x] = g_q[(b * T + t) * C + h * D + dd];
    }
    __syncthreads();
    int c = ch * 128 + threadIdx.x;
    float a0 = 0.f, a1 = 0.f;
    #pragma unroll 8
    for (int dd = 0; dd < D; dd++) {
        float w = kv_w[(long)(h * D + dd) * C + c];
        a0 += qs[dd] * w;
        a1 += qs[D + dd] * w;
    }
    g_qk[((long)(0 * J + j)) * C + c] = a0;
    g_qk[((long)(1 * J + j)) * C + c] = a1;
}

// ---------------- K3: partial attn over a c-quarter -------------------------
// grid (64 m-tiles, B, 4 c-quarters) = 512 CTAs, occ 4.
#define CHUNK 32
#define NCH   (CPER / CHUNK)           // 6
#define QK_FL (48 * CHUNK)             // 1536
#define FSTR  34
#define STAGE_FL (QK_FL + 64 * FSTR)   // 3712 floats = 14848 B/stage
__global__ __launch_bounds__(256, 4) void k_attn(const float* __restrict__ x) {
    extern __shared__ __align__(16) float sm[];   // 2 * STAGE_FL floats
    const int b  = blockIdx.y;
    const int m0 = blockIdx.x * 64;
    const int cs = blockIdx.z;
    const int tid  = threadIdx.x;
    const int warp = tid >> 5;
    const int lane = tid & 31;
    const int cr = tid >> 4;      // copy row base 0..15
    const int cp0 = tid & 15;     // copy pair    0..15

    const float* qsrc0 = g_qk + (long)b * J * C + cs * CPER
                       + (long)cr * C + cp0 * 2;               // +u*16*C
    const float* fsrc0 = x + ((long)b * NTOK + T + m0) * C + cs * CPER
                       + (long)cr * C + cp0 * 2;               // +u*16*C
    unsigned qdst0 = (unsigned)__cvta_generic_to_shared(
                         &sm[cr * CHUNK + cp0 * 2]);           // +u*2048B
    unsigned fdst0 = (unsigned)__cvta_generic_to_shared(
                         &sm[QK_FL + cr * FSTR + cp0 * 2]);    // +u*2176B

    unsigned long long acc[6][2];
    #pragma unroll
    for (int i = 0; i < 6; i++) { acc[i][0] = 0ull; acc[i][1] = 0ull; }

    #pragma unroll
    for (int u = 0; u < 3; u++) cp8(qdst0 + u * 2048, qsrc0 + u * 16 * C);
    #pragma unroll
    for (int u = 0; u < 4; u++) cp8(fdst0 + u * 2176, fsrc0 + u * 16 * C);
    asm volatile("cp.async.commit_group;\n" ::: "memory");

    for (int ic = 0; ic < NCH; ic++) {
        if (ic < NCH - 1) {
            unsigned so = ((ic + 1) & 1) * (unsigned)(STAGE_FL * 4);
            int cc = (ic + 1) * CHUNK;
            #pragma unroll
            for (int u = 0; u < 3; u++)
                cp8(qdst0 + so + u * 2048, qsrc0 + cc + u * 16 * C);
            #pragma unroll
            for (int u = 0; u < 4; u++)
                cp8(fdst0 + so + u * 2176, fsrc0 + cc + u * 16 * C);
            asm volatile("cp.async.commit_group;\n" ::: "memory");
            asm volatile("cp.async.wait_group 1;\n" ::: "memory");
        } else {
            asm volatile("cp.async.wait_group 0;\n" ::: "memory");
        }
        __syncthreads();
        const float* s_qk = sm + (ic & 1) * STAGE_FL;
        const float* s_ft = s_qk + QK_FL;
        #pragma unroll
        for (int cp = 0; cp < 16; cp++) {
            unsigned long long f0 =
                *(const unsigned long long*)&s_ft[lane * FSTR + cp * 2];
            unsigned long long f1 =
                *(const unsigned long long*)&s_ft[(lane + 32) * FSTR + cp * 2];
            #pragma unroll
            for (int i = 0; i < 6; i++) {
                unsigned long long qv =
                    *(const unsigned long long*)&s_qk[(warp * 6 + i) * CHUNK + cp * 2];
                ffma2(acc[i][0], qv, f0);
                ffma2(acc[i][1], qv, f1);
            }
        }
        __syncthreads();
    }
    #pragma unroll
    for (int i = 0; i < 6; i++) {
        int j = warp * 6 + i;
        float* row = g_attn2[cs] + ((long)(b * J + j)) * M + m0;
        U64F2 u0; u0.u = acc[i][0];
        U64F2 u1; u1.u = acc[i][1];
        row[lane]      = (u0.f.x + u0.f.y) * SCALE;
        row[lane + 32] = (u1.f.x + u1.f.y) * SCALE;
    }
}

// ---------------- K4a: stage-1 top-2 per (row, m-tile) ----------------------
__device__ __forceinline__ bool better(float v, int i, float bv, int bi) {
    return (v > bv) || (v == bv && (unsigned)i < (unsigned)bi);
}
__global__ __launch_bounds__(256) void k_top2a() {
    const int row   = blockIdx.y;          // 0..95
    const int mtile = blockIdx.x;          // 0..7
    const long base = (long)row * M + mtile * MTS;
    const float* r0 = g_attn2[0] + base;
    const float* r1 = g_attn2[1] + base;
    const float* r2 = g_attn2[2] + base;
    const float* r3 = g_attn2[3] + base;
    int tid = threadIdx.x;
    int mm = tid * 2;                      // 0..510 within tile
    float2 a0 = *(const float2*)&r0[mm];
    float2 a1 = *(const float2*)&r1[mm];
    float2 a2 = *(const float2*)&r2[mm];
    float2 a3 = *(const float2*)&r3[mm];
    int gm = mtile * MTS + mm;             // global m index
    float va = (a0.x + a1.x) + (a2.x + a3.x);
    float vb = (a0.y + a1.y) + (a2.y + a3.y);
    float v0, v1; int i0, i1;
    if (better(vb, gm + 1, va, gm)) { v0 = vb; i0 = gm + 1; v1 = va; i1 = gm; }
    else                            { v0 = va; i0 = gm;     v1 = vb; i1 = gm + 1; }

    __shared__ float sv0[256], sv1[256];
    __shared__ int   si0[256], si1[256];
    sv0[tid] = v0; si0[tid] = i0;
    sv1[tid] = v1; si1[tid] = i1;
    __syncthreads();
    #pragma unroll
    for (int s = 128; s >= 1; s >>= 1) {
        if (tid < s) {
            float p0 = sv0[tid], p1 = sv1[tid];
            int   ja = si0[tid], jb = si1[tid];
            float c0 = sv0[tid + s], c1 = sv1[tid + s];
            int   jc = si0[tid + s], jd = si1[tid + s];
            float n0, n1; int m0i, m1i;
            if (better(p0, ja, c0, jc)) {
                n0 = p0; m0i = ja;
                if (better(p1, jb, c0, jc)) { n1 = p1; m1i = jb; }
                else                        { n1 = c0; m1i = jc; }
            } else {
                n0 = c0; m0i = jc;
                if (better(p0, ja, c1, jd)) { n1 = p0; m1i = ja; }
                else                        { n1 = c1; m1i = jd; }
            }
            sv0[tid] = n0; si0[tid] = m0i;
            sv1[tid] = n1; si1[tid] = m1i;
        }
        __syncthreads();
    }
    if (tid == 0) {
        g_cv[row][mtile][0] = sv0[0];
        g_cv[row][mtile][1] = sv1[0];
        g_ci[row][mtile][0] = si0[0];
        g_ci[row][mtile][1] = si1[0];
    }
}

// ---------------- K4b: stage-2 merge 8 candidate pairs + softmax ------------
__global__ __launch_bounds__(32) void k_top2b() {
    const int row = blockIdx.x;
    int lane = threadIdx.x;
    float v0 = -__int_as_float(0x7f800000), v1 = v0;
    int i0 = -1, i1 = -1;
    if (lane < MT) {
        v0 = g_cv[row][lane][0]; i0 = g_ci[row][lane][0];
        v1 = g_cv[row][lane][1]; i1 = g_ci[row][lane][1];
    }
    #pragma unroll
    for (int s = 4; s >= 1; s >>= 1) {
        float c0 = __shfl_down_sync(0xffffffffu, v0, s);
        float c1 = __shfl_down_sync(0xffffffffu, v1, s);
        int   jc = __shfl_down_sync(0xffffffffu, i0, s);
        int   jd = __shfl_down_sync(0xffffffffu, i1, s);
        float n0, n1; int m0i, m1i;
        if (better(v0, i0, c0, jc)) {
            n0 = v0; m0i = i0;
            if (better(v1, i1, c0, jc)) { n1 = v1; m1i = i1; }
            else                        { n1 = c0; m1i = jc; }
        } else {
            n0 = c0; m0i = jc;
            if (better(v0, i0, c1, jd)) { n1 = v0; m1i = i0; }
            else                        { n1 = c1; m1i = jd; }
        }
        v0 = n0; i0 = m0i; v1 = n1; i1 = m1i;
    }
    if (lane == 0) {
        float e1 = __expf(v1 - v0);
        float inv = 1.f / (1.f + e1);
        g_topi[row * K + 0] = i0;
        g_topi[row * K + 1] = i1;
        g_topw[row * K + 0] = inv;
        g_topw[row * K + 1] = e1 * inv;
    }
}

// ---------------- K5: both selections of (b,j) in one block -----------------
__global__ __launch_bounds__(256) void k_select(const float* __restrict__ x,
                                                const float* __restrict__ kv_w,
                                                const float* __restrict__ experts_w,
                                                float* __restrict__ out) {
    int b = blockIdx.x / J;
    int j = blockIdx.x % J;
    int t = j & 3, h = j >> 2;
    int   m0 = g_topi[(b * J + j) * K + 0];
    int   m1 = g_topi[(b * J + j) * K + 1];
    float w0 = g_topw[(b * J + j) * K + 0];
    float w1 = g_topw[(b * J + j) * K + 1];
    int warp = threadIdx.x >> 5, lane = threadIdx.x & 31;
    __shared__ __align__(16) float f0s[C], f1s[C];
    for (int i = threadIdx.x; i < C; i += 256) {
        f0s[i] = x[((long)b * NTOK + T + m0) * C + i];
        f1s[i] = x[((long)b * NTOK + T + m1) * C + i];
    }
    __syncthreads();

    // (a) v rows dd = warp*8 + i, all 8 rows accumulated in one c-pass
    {
        const float* kw = kv_w + (long)(C + h * D + warp * 8) * C;
        float a0[8], a1[8];
        #pragma unroll
        for (int i = 0; i < 8; i++) { a0[i] = 0.f; a1[i] = 0.f; }
        #pragma unroll 2
        for (int c = lane; c < C; c += 32) {
            float f0 = f0s[c], f1 = f1s[c];
            #pragma unroll
            for (int i = 0; i < 8; i++) {
                float w = kw[(long)i * C + c];
                a0[i] += f0 * w;
                a1[i] += f1 * w;
            }
        }
        #pragma unroll
        for (int i = 0; i < 8; i++) {
            float s0 = warp_sum(a0[i]);
            float s1 = warp_sum(a1[i]);
            if (lane == 0)
                g_attn_token[(b * T + t) * C + h * D + warp * 8 + i] =
                    w0 * s0 + w1 * s1;
        }
    }

    // (b) expert projection: warps 0-3 -> k=0, warps 4-7 -> k=1
    int kk = warp >> 2;
    const float* fs = kk ? f1s : f0s;
    int   m = kk ? m1 : m0;
    float w = kk ? w1 : w0;
    float4 fa[16];
    const float4* fh4 = (const float4*)(fs + h * D);
    #pragma unroll
    for (int q = 0; q < 16; q++) fa[q] = fh4[q];
    int wtid = (warp & 3) * 32 + lane;  // 0..127
    for (int o = wtid; o < C; o += 128) {
        const float4* ew4 =
            (const float4*)(experts_w + ((long)t * C + o) * C + h * D);
        float s = 0.f;
        #pragma unroll
        for (int q = 0; q < 16; q++) {
            float4 e = ew4[q];
            s += fa[q].x * e.x + fa[q].y * e.y + fa[q].z * e.z + fa[q].w * e.w;
        }
        atomicAdd(&out[((long)b * NTOK + T + m) * C + o], w * s);
    }
}

// ---------------- K6: token_output[b,t,o] = <attn_token[b,t,:], experts_w[t,o,:]>
__global__ __launch_bounds__(256) void k_token(const float* __restrict__ experts_w,
                                               float* __restrict__ out) {
    int og = blockIdx.x % 96;
    int t  = blockIdx.x / 96;
    __shared__ float as[2 * C];
    for (int i = threadIdx.x; i < 2 * C; i += 256) {
        int b = i / C, c = i % C;
        as[i] = g_attn_token[(b * T + t) * C + c];
    }
    __syncthreads();
    int warp = threadIdx.x >> 5, lane = threadIdx.x & 31;
    int o = og * 8 + warp;
    const float* wrow = experts_w + ((long)t * C + o) * C;
    float s0 = 0.f, s1 = 0.f;
    #pragma unroll 8
    for (int c = lane; c < C; c += 32) {
        float w = wrow[c];
        s0 += as[c] * w;
        s1 += as[C + c] * w;
    }
    s0 = warp_sum(s0);
    s1 = warp_sum(s1);
    if (lane == 0) {
        out[((long)0 * NTOK + t) * C + o] = s0;
        out[((long)1 * NTOK + t) * C + o] = s1;
    }
}

// ---------------- launch ----------------------------------------------------
extern "C" void kernel_launch(void* const* d_in, const int* in_sizes, int n_in,
                              void* d_out, int out_size) {
    const float* x         = (const float*)d_in[0];
    const float* qs_w      = (const float*)d_in[1];
    const float* kv_w      = (const float*)d_in[2];
    const float* experts_w = (const float*)d_in[3];
    float* out = (float*)d_out;

    cudaMemsetAsync(out, 0, (size_t)out_size * sizeof(float));
    k_q<<<384, 256>>>(x, qs_w);
    k_qk<<<288, 128>>>(kv_w);
    k_attn<<<dim3(64, B, CSP), 256, 2 * STAGE_FL * 4>>>(x);
    k_top2a<<<dim3(MT, B * J), 256>>>();
    k_top2b<<<B * J, 32>>>();
    k_select<<<96, 256>>>(x, kv_w, experts_w, out);
    k_token<<<384, 256>>>(experts_w, out);
}